// round 4
// baseline (speedup 1.0000x reference)
#include <cuda_runtime.h>
#include <math.h>

// Problem constants
#define Bb 8
#define Cc 1152
#define Hh 32
#define Ww 32
#define Nn 1024   // H*W

// ---------------- scratch (static device globals: allowed) ----------------
__device__ float g_alpha[Bb * Nn];
__device__ float g_beta [Bb * Nn];
__device__ float g_gamma[Bb * Nn];
__device__ float g_S[(size_t)Bb * Nn * Nn];   // row-softmax s, then overwritten with attention A

// ---------------- kernel 1: fundamental matrix + per-line coefficients ----
// F = K2^{-T} * skew(t) * R * K1^{-1}   (no SVD: sing. values of skew(t)R are (s,s,0))
// For line j (pixel (x_j, y_j)): l = F u_j, a'=l0/l2, b'=l1/l2,
// store unit-normalized (alpha, beta, gamma) = (a', b', 1) / sqrt(a'^2+b'^2)
// so that d_epi[i,j] = |alpha_j*x_i + beta_j*y_i + gamma_j|.
__global__ void k_coef(const float* __restrict__ K1, const float* __restrict__ K2,
                       const float* __restrict__ R,  const float* __restrict__ T)
{
    int b = blockIdx.x;
    __shared__ float F[9];
    if (threadIdx.x == 0) {
        const float* k1 = K1 + b * 9;
        const float* k2 = K2 + b * 9;
        const float* r  = R  + b * 9;
        const float* tv = T  + b * 3;
        float t0 = tv[0], t1 = tv[1], t2 = tv[2];
        float E[9];
        #pragma unroll
        for (int c = 0; c < 3; c++) {
            float r0 = r[0 * 3 + c], r1 = r[1 * 3 + c], r2 = r[2 * 3 + c];
            E[0 * 3 + c] = -t2 * r1 + t1 * r2;
            E[1 * 3 + c] =  t2 * r0 - t0 * r2;
            E[2 * 3 + c] = -t1 * r0 + t0 * r1;
        }
        float fx2 = k2[0], fy2 = k2[4], cx2 = k2[2], cy2 = k2[5];
        float M[9];
        #pragma unroll
        for (int c = 0; c < 3; c++) {
            M[0 * 3 + c] = E[0 * 3 + c] / fx2;
            M[1 * 3 + c] = E[1 * 3 + c] / fy2;
            M[2 * 3 + c] = -cx2 / fx2 * E[0 * 3 + c] - cy2 / fy2 * E[1 * 3 + c] + E[2 * 3 + c];
        }
        float fx1 = k1[0], fy1 = k1[4], cx1 = k1[2], cy1 = k1[5];
        #pragma unroll
        for (int rr = 0; rr < 3; rr++) {
            float m0 = M[rr * 3 + 0], m1 = M[rr * 3 + 1], m2 = M[rr * 3 + 2];
            F[rr * 3 + 0] = m0 / fx1;
            F[rr * 3 + 1] = m1 / fy1;
            F[rr * 3 + 2] = -cx1 / fx1 * m0 - cy1 / fy1 * m1 + m2;
        }
    }
    __syncthreads();
    for (int j = threadIdx.x; j < Nn; j += blockDim.x) {
        float x = (float)(j / Ww);   // combined[0] = ix = row index
        float y = (float)(j % Ww);   // combined[1] = iy = col index
        float l0 = F[0] * x + F[1] * y + F[2];
        float l1 = F[3] * x + F[4] * y + F[5];
        float l2 = F[6] * x + F[7] * y + F[8];
        float ap = l0 / l2;
        float bp = l1 / l2;
        float rn = rsqrtf(ap * ap + bp * bp);
        g_alpha[b * Nn + j] = ap * rn;
        g_beta [b * Nn + j] = bp * rn;
        g_gamma[b * Nn + j] = rn;
    }
}

// ---------------- kernel 2: row softmax s[i,j] = softmax_j(5*d_epi) -------
__global__ void k_row()
{
    int i = blockIdx.x;
    int b = blockIdx.y;
    float x = (float)(i / Ww);
    float y = (float)(i % Ww);
    const float* al = g_alpha + b * Nn;
    const float* be = g_beta  + b * Nn;
    const float* ga = g_gamma + b * Nn;

    float v[4];
    float m = -1e30f;
    #pragma unroll
    for (int k = 0; k < 4; k++) {
        int j = threadIdx.x + k * 256;
        float d = fabsf(al[j] * x + be[j] * y + ga[j]);
        v[k] = 5.0f * d;
        m = fmaxf(m, v[k]);
    }
    __shared__ float red[8];
    #pragma unroll
    for (int o = 16; o; o >>= 1) m = fmaxf(m, __shfl_xor_sync(0xffffffffu, m, o));
    if ((threadIdx.x & 31) == 0) red[threadIdx.x >> 5] = m;
    __syncthreads();
    float bm = red[0];
    #pragma unroll
    for (int w = 1; w < 8; w++) bm = fmaxf(bm, red[w]);

    float e[4];
    float z = 0.0f;
    #pragma unroll
    for (int k = 0; k < 4; k++) { e[k] = __expf(v[k] - bm); z += e[k]; }
    __syncthreads();
    #pragma unroll
    for (int o = 16; o; o >>= 1) z += __shfl_xor_sync(0xffffffffu, z, o);
    if ((threadIdx.x & 31) == 0) red[threadIdx.x >> 5] = z;
    __syncthreads();
    float bz = 0.0f;
    #pragma unroll
    for (int w = 0; w < 8; w++) bz += red[w];
    float inv = 1.0f / bz;

    float* row = g_S + ((size_t)(b * Nn + i)) * Nn;
    #pragma unroll
    for (int k = 0; k < 4; k++) row[threadIdx.x + k * 256] = e[k] * inv;
}

// ---------------- kernel 3: column softmax A[i,j] = softmax_i(-s[i,j]) ----
// In place on g_S: A = exp(min_i s - s) / sum_i exp(min_i s - s)
__global__ void k_col()
{
    int b  = blockIdx.y;
    int j  = blockIdx.x * 32 + threadIdx.x;
    int ty = threadIdx.y;   // 0..7
    float* S = g_S + (size_t)b * Nn * Nn;

    // online (min, sum exp(min - s)) over this thread's strided rows
    float m = 1e30f, acc = 0.0f;
    for (int i = ty; i < Nn; i += 8) {
        float val = S[(size_t)i * Nn + j];
        if (val < m) { acc = acc * __expf(val - m) + 1.0f; m = val; }
        else         { acc += __expf(m - val); }
    }
    __shared__ float sm[8][32];
    __shared__ float ss[8][32];
    sm[ty][threadIdx.x] = m;
    ss[ty][threadIdx.x] = acc;
    __syncthreads();
    if (ty == 0) {
        float M  = sm[0][threadIdx.x];
        float Sv = ss[0][threadIdx.x];
        #pragma unroll
        for (int g = 1; g < 8; g++) {
            float m2 = sm[g][threadIdx.x], s2 = ss[g][threadIdx.x];
            float Mn = fminf(M, m2);
            Sv = Sv * __expf(Mn - M) + s2 * __expf(Mn - m2);
            M = Mn;
        }
        sm[0][threadIdx.x] = M;
        ss[0][threadIdx.x] = 1.0f / Sv;
    }
    __syncthreads();
    float M    = sm[0][threadIdx.x];
    float invS = ss[0][threadIdx.x];
    for (int i = ty; i < Nn; i += 8) {
        size_t idx = (size_t)i * Nn + j;
        S[idx] = __expf(M - S[idx]) * invS;
    }
}

// ---------------- kernel 4: out[b,i,c] = sum_j A[i,j] * f[c,j] (NT SGEMM) --
#define BM 128
#define BN 128
#define BK 16

__global__ __launch_bounds__(256, 2)
void k_gemm(const float* __restrict__ f, float* __restrict__ out)
{
    int b  = blockIdx.z;
    int m0 = blockIdx.y * BM;   // i tile
    int n0 = blockIdx.x * BN;   // c tile
    const float* Ag = g_S + (size_t)b * Nn * Nn;
    const float* Bg = f   + (size_t)b * Cc * Nn;
    float*       Og = out + (size_t)b * Nn * Cc;

    __shared__ float As[2][BK][BM + 4];
    __shared__ float Bs[2][BK][BN + 4];

    int tid  = threadIdx.x;
    int tx   = tid & 15;
    int ty   = tid >> 4;
    int lrow = tid >> 2;          // 0..63
    int lk   = (tid & 3) << 2;    // 0,4,8,12

    float acc[8][8];
    #pragma unroll
    for (int i = 0; i < 8; i++)
        #pragma unroll
        for (int j = 0; j < 8; j++) acc[i][j] = 0.0f;

    float4 pa0, pa1, pb0, pb1;

    // stage 0
    pa0 = *(const float4*)(Ag + (size_t)(m0 + lrow)      * Nn + lk);
    pa1 = *(const float4*)(Ag + (size_t)(m0 + lrow + 64) * Nn + lk);
    pb0 = *(const float4*)(Bg + (size_t)(n0 + lrow)      * Nn + lk);
    pb1 = *(const float4*)(Bg + (size_t)(n0 + lrow + 64) * Nn + lk);
    As[0][lk + 0][lrow] = pa0.x; As[0][lk + 1][lrow] = pa0.y; As[0][lk + 2][lrow] = pa0.z; As[0][lk + 3][lrow] = pa0.w;
    As[0][lk + 0][lrow + 64] = pa1.x; As[0][lk + 1][lrow + 64] = pa1.y; As[0][lk + 2][lrow + 64] = pa1.z; As[0][lk + 3][lrow + 64] = pa1.w;
    Bs[0][lk + 0][lrow] = pb0.x; Bs[0][lk + 1][lrow] = pb0.y; Bs[0][lk + 2][lrow] = pb0.z; Bs[0][lk + 3][lrow] = pb0.w;
    Bs[0][lk + 0][lrow + 64] = pb1.x; Bs[0][lk + 1][lrow + 64] = pb1.y; Bs[0][lk + 2][lrow + 64] = pb1.z; Bs[0][lk + 3][lrow + 64] = pb1.w;
    __syncthreads();

    int buf = 0;
    for (int kt = 0; kt < Nn / BK; kt++) {
        int knext = (kt + 1) * BK;
        if (knext < Nn) {
            pa0 = *(const float4*)(Ag + (size_t)(m0 + lrow)      * Nn + knext + lk);
            pa1 = *(const float4*)(Ag + (size_t)(m0 + lrow + 64) * Nn + knext + lk);
            pb0 = *(const float4*)(Bg + (size_t)(n0 + lrow)      * Nn + knext + lk);
            pb1 = *(const float4*)(Bg + (size_t)(n0 + lrow + 64) * Nn + knext + lk);
        }
        #pragma unroll
        for (int kk = 0; kk < BK; kk++) {
            float a[8], bb[8];
            *(float4*)(a)      = *(const float4*)&As[buf][kk][ty * 8];
            *(float4*)(a + 4)  = *(const float4*)&As[buf][kk][ty * 8 + 4];
            *(float4*)(bb)     = *(const float4*)&Bs[buf][kk][tx * 8];
            *(float4*)(bb + 4) = *(const float4*)&Bs[buf][kk][tx * 8 + 4];
            #pragma unroll
            for (int i = 0; i < 8; i++)
                #pragma unroll
                for (int j = 0; j < 8; j++)
                    acc[i][j] = fmaf(a[i], bb[j], acc[i][j]);
        }
        if (knext < Nn) {
            int nb = buf ^ 1;
            As[nb][lk + 0][lrow] = pa0.x; As[nb][lk + 1][lrow] = pa0.y; As[nb][lk + 2][lrow] = pa0.z; As[nb][lk + 3][lrow] = pa0.w;
            As[nb][lk + 0][lrow + 64] = pa1.x; As[nb][lk + 1][lrow + 64] = pa1.y; As[nb][lk + 2][lrow + 64] = pa1.z; As[nb][lk + 3][lrow + 64] = pa1.w;
            Bs[nb][lk + 0][lrow] = pb0.x; Bs[nb][lk + 1][lrow] = pb0.y; Bs[nb][lk + 2][lrow] = pb0.z; Bs[nb][lk + 3][lrow] = pb0.w;
            Bs[nb][lk + 0][lrow + 64] = pb1.x; Bs[nb][lk + 1][lrow + 64] = pb1.y; Bs[nb][lk + 2][lrow + 64] = pb1.z; Bs[nb][lk + 3][lrow + 64] = pb1.w;
        }
        __syncthreads();
        buf ^= 1;
    }

    #pragma unroll
    for (int i = 0; i < 8; i++) {
        float* orow = Og + (size_t)(m0 + ty * 8 + i) * Cc + n0 + tx * 8;
        float4 r0 = make_float4(acc[i][0], acc[i][1], acc[i][2], acc[i][3]);
        float4 r1 = make_float4(acc[i][4], acc[i][5], acc[i][6], acc[i][7]);
        *(float4*)(orow)     = r0;
        *(float4*)(orow + 4) = r1;
    }
}

// ---------------- entry point ---------------------------------------------
extern "C" void kernel_launch(void* const* d_in, const int* in_sizes, int n_in,
                              void* d_out, int out_size)
{
    // metadata order: f_tar(0, unused), f_src(1), K1(2), K2(3), R(4), t(5)
    const float* f_src = (const float*)d_in[1];
    const float* K1    = (const float*)d_in[2];
    const float* K2    = (const float*)d_in[3];
    const float* R     = (const float*)d_in[4];
    const float* T     = (const float*)d_in[5];
    float* out = (float*)d_out;

    k_coef<<<Bb, 256>>>(K1, K2, R, T);
    k_row<<<dim3(Nn, Bb), 256>>>();
    k_col<<<dim3(Nn / 32, Bb), dim3(32, 8)>>>();
    k_gemm<<<dim3(Cc / BN, Nn / BM, Bb), 256>>>(f_src, out);
}

// round 6
// speedup vs baseline: 2.0760x; 2.0760x over previous
#include <cuda_runtime.h>
#include <cuda_bf16.h>
#include <cstdint>
#include <math.h>

// Problem constants
#define Bb 8
#define Cc 1152
#define Hh 32
#define Ww 32
#define Nn 1024   // H*W

// ---------------- scratch (static device globals: allowed) ----------------
__device__ float g_alpha[Bb * Nn];
__device__ float g_beta [Bb * Nn];
__device__ float g_gamma[Bb * Nn];
__device__ float g_S[(size_t)Bb * Nn * Nn];               // row-softmax s (fp32 intermediate)
__device__ __nv_bfloat16 g_Ahi[(size_t)Bb * Nn * Nn];     // attention A split
__device__ __nv_bfloat16 g_Alo[(size_t)Bb * Nn * Nn];
__device__ __nv_bfloat16 g_fhi[(size_t)Bb * Cc * Nn];     // f_src split
__device__ __nv_bfloat16 g_flo[(size_t)Bb * Cc * Nn];

// ======================= generic-PTX helpers ===============================
__device__ __forceinline__ uint32_t smem_to_u32(const void* p) {
    uint32_t a;
    asm("{ .reg .u64 t; cvta.to.shared.u64 t, %1; cvt.u32.u64 %0, t; }" : "=r"(a) : "l"(p));
    return a;
}
__device__ __forceinline__ void cp16(uint32_t s, const void* g) {
    asm volatile("cp.async.cg.shared.global [%0], [%1], 16;" :: "r"(s), "l"(g));
}
#define CP_COMMIT() asm volatile("cp.async.commit_group;" ::: "memory")
#define CP_WAIT(n)  asm volatile("cp.async.wait_group %0;" :: "n"(n) : "memory")

__device__ __forceinline__ void ldsm_x4(uint32_t* r, uint32_t addr) {
    asm volatile("ldmatrix.sync.aligned.m8n8.x4.shared.b16 {%0,%1,%2,%3}, [%4];"
                 : "=r"(r[0]), "=r"(r[1]), "=r"(r[2]), "=r"(r[3]) : "r"(addr));
}
__device__ __forceinline__ void mma16816(float* c, const uint32_t* a, const uint32_t* b) {
    asm volatile(
        "mma.sync.aligned.m16n8k16.row.col.f32.bf16.bf16.f32 "
        "{%0,%1,%2,%3}, {%4,%5,%6,%7}, {%8,%9}, {%0,%1,%2,%3};"
        : "+f"(c[0]), "+f"(c[1]), "+f"(c[2]), "+f"(c[3])
        : "r"(a[0]), "r"(a[1]), "r"(a[2]), "r"(a[3]), "r"(b[0]), "r"(b[1]));
}

// ---------------- kernel 1: fundamental matrix + per-line coefficients ----
__global__ void k_coef(const float* __restrict__ K1, const float* __restrict__ K2,
                       const float* __restrict__ R,  const float* __restrict__ T)
{
    int b = blockIdx.x;
    __shared__ float F[9];
    if (threadIdx.x == 0) {
        const float* k1 = K1 + b * 9;
        const float* k2 = K2 + b * 9;
        const float* r  = R  + b * 9;
        const float* tv = T  + b * 3;
        float t0 = tv[0], t1 = tv[1], t2 = tv[2];
        float E[9];
        #pragma unroll
        for (int c = 0; c < 3; c++) {
            float r0 = r[0 * 3 + c], r1 = r[1 * 3 + c], r2 = r[2 * 3 + c];
            E[0 * 3 + c] = -t2 * r1 + t1 * r2;
            E[1 * 3 + c] =  t2 * r0 - t0 * r2;
            E[2 * 3 + c] = -t1 * r0 + t0 * r1;
        }
        float fx2 = k2[0], fy2 = k2[4], cx2 = k2[2], cy2 = k2[5];
        float M[9];
        #pragma unroll
        for (int c = 0; c < 3; c++) {
            M[0 * 3 + c] = E[0 * 3 + c] / fx2;
            M[1 * 3 + c] = E[1 * 3 + c] / fy2;
            M[2 * 3 + c] = -cx2 / fx2 * E[0 * 3 + c] - cy2 / fy2 * E[1 * 3 + c] + E[2 * 3 + c];
        }
        float fx1 = k1[0], fy1 = k1[4], cx1 = k1[2], cy1 = k1[5];
        #pragma unroll
        for (int rr = 0; rr < 3; rr++) {
            float m0 = M[rr * 3 + 0], m1 = M[rr * 3 + 1], m2 = M[rr * 3 + 2];
            F[rr * 3 + 0] = m0 / fx1;
            F[rr * 3 + 1] = m1 / fy1;
            F[rr * 3 + 2] = -cx1 / fx1 * m0 - cy1 / fy1 * m1 + m2;
        }
    }
    __syncthreads();
    for (int j = threadIdx.x; j < Nn; j += blockDim.x) {
        float x = (float)(j / Ww);
        float y = (float)(j % Ww);
        float l0 = F[0] * x + F[1] * y + F[2];
        float l1 = F[3] * x + F[4] * y + F[5];
        float l2 = F[6] * x + F[7] * y + F[8];
        float ap = l0 / l2;
        float bp = l1 / l2;
        float rn = rsqrtf(ap * ap + bp * bp);
        g_alpha[b * Nn + j] = ap * rn;
        g_beta [b * Nn + j] = bp * rn;
        g_gamma[b * Nn + j] = rn;
    }
}

// ---------------- kernel 2: row softmax s[i,j] = softmax_j(5*d_epi) -------
__global__ void k_row()
{
    int i = blockIdx.x;
    int b = blockIdx.y;
    float x = (float)(i / Ww);
    float y = (float)(i % Ww);
    const float* al = g_alpha + b * Nn;
    const float* be = g_beta  + b * Nn;
    const float* ga = g_gamma + b * Nn;

    float v[4];
    float m = -1e30f;
    #pragma unroll
    for (int k = 0; k < 4; k++) {
        int j = threadIdx.x + k * 256;
        float d = fabsf(al[j] * x + be[j] * y + ga[j]);
        v[k] = 5.0f * d;
        m = fmaxf(m, v[k]);
    }
    __shared__ float red[8];
    #pragma unroll
    for (int o = 16; o; o >>= 1) m = fmaxf(m, __shfl_xor_sync(0xffffffffu, m, o));
    if ((threadIdx.x & 31) == 0) red[threadIdx.x >> 5] = m;
    __syncthreads();
    float bm = red[0];
    #pragma unroll
    for (int w = 1; w < 8; w++) bm = fmaxf(bm, red[w]);

    float e[4];
    float z = 0.0f;
    #pragma unroll
    for (int k = 0; k < 4; k++) { e[k] = __expf(v[k] - bm); z += e[k]; }
    __syncthreads();
    #pragma unroll
    for (int o = 16; o; o >>= 1) z += __shfl_xor_sync(0xffffffffu, z, o);
    if ((threadIdx.x & 31) == 0) red[threadIdx.x >> 5] = z;
    __syncthreads();
    float bz = 0.0f;
    #pragma unroll
    for (int w = 0; w < 8; w++) bz += red[w];
    float inv = 1.0f / bz;

    float* row = g_S + ((size_t)(b * Nn + i)) * Nn;
    #pragma unroll
    for (int k = 0; k < 4; k++) row[threadIdx.x + k * 256] = e[k] * inv;
}

// ---------------- kernel 3: column softmax -> A split into bf16 hi/lo -----
__global__ void k_col()
{
    int b  = blockIdx.y;
    int j  = blockIdx.x * 32 + threadIdx.x;
    int ty = threadIdx.y;   // 0..7
    const float* S = g_S + (size_t)b * Nn * Nn;
    __nv_bfloat16* Ah = g_Ahi + (size_t)b * Nn * Nn;
    __nv_bfloat16* Al = g_Alo + (size_t)b * Nn * Nn;

    float m = 1e30f, acc = 0.0f;
    for (int i = ty; i < Nn; i += 8) {
        float val = S[(size_t)i * Nn + j];
        if (val < m) { acc = acc * __expf(val - m) + 1.0f; m = val; }
        else         { acc += __expf(m - val); }
    }
    __shared__ float sm[8][32];
    __shared__ float ss[8][32];
    sm[ty][threadIdx.x] = m;
    ss[ty][threadIdx.x] = acc;
    __syncthreads();
    if (ty == 0) {
        float M  = sm[0][threadIdx.x];
        float Sv = ss[0][threadIdx.x];
        #pragma unroll
        for (int g = 1; g < 8; g++) {
            float m2 = sm[g][threadIdx.x], s2 = ss[g][threadIdx.x];
            float Mn = fminf(M, m2);
            Sv = Sv * __expf(Mn - M) + s2 * __expf(Mn - m2);
            M = Mn;
        }
        sm[0][threadIdx.x] = M;
        ss[0][threadIdx.x] = 1.0f / Sv;
    }
    __syncthreads();
    float M    = sm[0][threadIdx.x];
    float invS = ss[0][threadIdx.x];
    for (int i = ty; i < Nn; i += 8) {
        size_t idx = (size_t)i * Nn + j;
        float v = __expf(M - S[idx]) * invS;
        __nv_bfloat16 h = __float2bfloat16(v);
        float lo = v - __bfloat162float(h);
        Ah[idx] = h;
        Al[idx] = __float2bfloat16(lo);
    }
}

// ---------------- kernel 3b: split f_src into bf16 hi/lo ------------------
__global__ void k_conv_f(const float* __restrict__ f)
{
    size_t n4 = (size_t)Bb * Cc * Nn / 4;
    for (size_t i = (size_t)blockIdx.x * blockDim.x + threadIdx.x; i < n4;
         i += (size_t)gridDim.x * blockDim.x) {
        float4 v = ((const float4*)f)[i];
        __nv_bfloat16 h0 = __float2bfloat16(v.x);
        __nv_bfloat16 h1 = __float2bfloat16(v.y);
        __nv_bfloat16 h2 = __float2bfloat16(v.z);
        __nv_bfloat16 h3 = __float2bfloat16(v.w);
        __nv_bfloat16 l0 = __float2bfloat16(v.x - __bfloat162float(h0));
        __nv_bfloat16 l1 = __float2bfloat16(v.y - __bfloat162float(h1));
        __nv_bfloat16 l2 = __float2bfloat16(v.z - __bfloat162float(h2));
        __nv_bfloat16 l3 = __float2bfloat16(v.w - __bfloat162float(h3));
        uint2 ph, pl;
        ph.x = (uint32_t)__bfloat16_as_ushort(h0) | ((uint32_t)__bfloat16_as_ushort(h1) << 16);
        ph.y = (uint32_t)__bfloat16_as_ushort(h2) | ((uint32_t)__bfloat16_as_ushort(h3) << 16);
        pl.x = (uint32_t)__bfloat16_as_ushort(l0) | ((uint32_t)__bfloat16_as_ushort(l1) << 16);
        pl.y = (uint32_t)__bfloat16_as_ushort(l2) | ((uint32_t)__bfloat16_as_ushort(l3) << 16);
        *(uint2*)(g_fhi + 4 * i) = ph;
        *(uint2*)(g_flo + 4 * i) = pl;
    }
}

// ---------------- kernel 4: mma.sync bf16 GEMM out = A @ f^T (3-term) -----
// Tile M=128 (i), N=128 (c), K streamed in 16 stages of 64.
// SMEM per stage: Ahi/Alo/Bhi/Blo each 128 rows x 128B (SW128 XOR swizzle) = 64KB.
// Double-buffered: 128KB dynamic SMEM. 8 warps: warp_m = wid&1 (64 rows),
// warp_n = wid>>1 (32 cols). Per warp per k16: 4 m16 x 4 n8 x 3 terms = 48 HMMA.
#define TILE_B   16384          // one 128x64 bf16 tile (swizzled, 128B rows)
#define STAGE_B  (4 * TILE_B)   // Ahi, Alo, Bhi, Blo
#define GEMM_SMEM (2 * STAGE_B) // 131072

__global__ void __launch_bounds__(256, 1) k_gemm_mma(float* __restrict__ out)
{
    extern __shared__ char smem[];
    const uint32_t sb = smem_to_u32(smem);
    const int tid  = threadIdx.x;
    const int wid  = tid >> 5;
    const int lane = tid & 31;
    const int b    = blockIdx.z;
    const int n0   = blockIdx.x * 128;   // c tile
    const int m0   = blockIdx.y * 128;   // i tile

    const __nv_bfloat16* Ah = g_Ahi + (size_t)b * Nn * Nn;
    const __nv_bfloat16* Al = g_Alo + (size_t)b * Nn * Nn;
    const __nv_bfloat16* Fh = g_fhi + (size_t)b * Cc * Nn;
    const __nv_bfloat16* Fl = g_flo + (size_t)b * Cc * Nn;

    // producer chunk mapping: 1024 16B chunks per tile, 4 per thread
    // chunk id = tid + q*256 -> row = id>>3, c = id&7; swizzled col = 16c ^ ((row&7)<<4)
    uint32_t p_soff[4];
    uint32_t p_row[4];
    #pragma unroll
    for (int q = 0; q < 4; q++) {
        int id  = tid + q * 256;
        int row = id >> 3;
        int c   = id & 7;
        p_row[q]  = row;
        p_soff[q] = (uint32_t)(row * 128 + ((16 * c) ^ ((row & 7) << 4)));
    }

    // MMA thread geometry
    const int warp_m = wid & 1;        // 0..1
    const int warp_n = wid >> 1;       // 0..3
    const int g  = lane >> 3;          // ldmatrix address group 0..3
    const int r  = lane & 7;
    uint32_t arow[4], brow[2];
    #pragma unroll
    for (int mt = 0; mt < 4; mt++)
        arow[mt] = (uint32_t)((warp_m * 64 + mt * 16 + (g & 1) * 8 + r) * 128);
    #pragma unroll
    for (int p = 0; p < 2; p++)
        brow[p] = (uint32_t)((warp_n * 32 + p * 16 + (g >> 1) * 8 + r) * 128);
    const uint32_t ka_half = (uint32_t)((g >> 1) << 4);   // A: k-halves on groups 2,3
    const uint32_t kb_half = (uint32_t)((g & 1) << 4);    // B: k-halves on groups 1,3
    const uint32_t rx = (uint32_t)(r << 4);               // swizzle XOR (row&7)<<4 == r<<4

    float acc[4][4][4];
    #pragma unroll
    for (int mt = 0; mt < 4; mt++)
        #pragma unroll
        for (int nt = 0; nt < 4; nt++)
            #pragma unroll
            for (int q = 0; q < 4; q++) acc[mt][nt][q] = 0.0f;

    // ---- issue a stage load (all 256 threads, 16 cp.async each) ----
    auto issue_load = [&](int buf, int s) {
        uint32_t base = sb + (uint32_t)buf * STAGE_B;
        int k0 = s * 64;
        #pragma unroll
        for (int q = 0; q < 4; q++) {
            uint32_t row = p_row[q];
            int gk = k0 + ((tid + q * 256) & 7) * 8;
            size_t gA = (size_t)(m0 + row) * Nn + gk;
            size_t gB = (size_t)(n0 + row) * Nn + gk;
            cp16(base + p_soff[q],               Ah + gA);
            cp16(base + TILE_B     + p_soff[q],  Al + gA);
            cp16(base + 2 * TILE_B + p_soff[q],  Fh + gB);
            cp16(base + 3 * TILE_B + p_soff[q],  Fl + gB);
        }
    };

    issue_load(0, 0);
    CP_COMMIT();

    int buf = 0;
    for (int s = 0; s < Nn / 64; s++) {
        if (s + 1 < Nn / 64) {
            issue_load(buf ^ 1, s + 1);
            CP_COMMIT();
            CP_WAIT(1);
        } else {
            CP_WAIT(0);
        }
        __syncthreads();

        uint32_t bA_hi = sb + (uint32_t)buf * STAGE_B;
        uint32_t bA_lo = bA_hi + TILE_B;
        uint32_t bB_hi = bA_hi + 2 * TILE_B;
        uint32_t bB_lo = bA_hi + 3 * TILE_B;

        #pragma unroll
        for (int kk = 0; kk < 4; kk++) {
            uint32_t ka = ((uint32_t)(kk * 32) + ka_half) ^ rx;
            uint32_t kb = ((uint32_t)(kk * 32) + kb_half) ^ rx;
            uint32_t ahi[4][4], alo[4][4];
            #pragma unroll
            for (int mt = 0; mt < 4; mt++) {
                ldsm_x4(ahi[mt], bA_hi + arow[mt] + ka);
                ldsm_x4(alo[mt], bA_lo + arow[mt] + ka);
            }
            uint32_t bhi[2][4], blo[2][4];
            #pragma unroll
            for (int p = 0; p < 2; p++) {
                ldsm_x4(bhi[p], bB_hi + brow[p] + kb);
                ldsm_x4(blo[p], bB_lo + brow[p] + kb);
            }
            #pragma unroll
            for (int mt = 0; mt < 4; mt++) {
                #pragma unroll
                for (int nt = 0; nt < 4; nt++) {
                    const uint32_t* bh = &bhi[nt >> 1][(nt & 1) * 2];
                    const uint32_t* bl = &blo[nt >> 1][(nt & 1) * 2];
                    mma16816(acc[mt][nt], ahi[mt], bh);
                    mma16816(acc[mt][nt], ahi[mt], bl);
                    mma16816(acc[mt][nt], alo[mt], bh);
                }
            }
        }
        __syncthreads();
        buf ^= 1;
    }

    // ---- epilogue: acc -> out[b, i, c] (out stride Cc) ----
    float* Og = out + (size_t)b * Nn * Cc;
    const int rbase = m0 + warp_m * 64 + (lane >> 2);
    const int cbase = n0 + warp_n * 32 + (lane & 3) * 2;
    #pragma unroll
    for (int mt = 0; mt < 4; mt++) {
        #pragma unroll
        for (int nt = 0; nt < 4; nt++) {
            int row = rbase + mt * 16;
            int col = cbase + nt * 8;
            float2 v0 = make_float2(acc[mt][nt][0], acc[mt][nt][1]);
            float2 v1 = make_float2(acc[mt][nt][2], acc[mt][nt][3]);
            *(float2*)(Og + (size_t)row * Cc + col)       = v0;
            *(float2*)(Og + (size_t)(row + 8) * Cc + col) = v1;
        }
    }
}

// ---------------- entry point ---------------------------------------------
extern "C" void kernel_launch(void* const* d_in, const int* in_sizes, int n_in,
                              void* d_out, int out_size)
{
    // metadata order: f_tar(0, unused), f_src(1), K1(2), K2(3), R(4), t(5)
    const float* f_src = (const float*)d_in[1];
    const float* K1    = (const float*)d_in[2];
    const float* K2    = (const float*)d_in[3];
    const float* R     = (const float*)d_in[4];
    const float* T     = (const float*)d_in[5];
    float* out = (float*)d_out;

    cudaFuncSetAttribute(k_gemm_mma, cudaFuncAttributeMaxDynamicSharedMemorySize, GEMM_SMEM);

    k_conv_f<<<1024, 256>>>(f_src);
    k_coef<<<Bb, 256>>>(K1, K2, R, T);
    k_row<<<dim3(Nn, Bb), 256>>>();
    k_col<<<dim3(Nn / 32, Bb), dim3(32, 8)>>>();
    k_gemm_mma<<<dim3(Cc / 128, Nn / 128, Bb), 256, GEMM_SMEM>>>(out);
}

// round 9
// speedup vs baseline: 2.4607x; 1.1853x over previous
#include <cuda_runtime.h>
#include <cuda_bf16.h>
#include <cstdint>
#include <math.h>

// Problem constants
#define Bb 8
#define Cc 1152
#define Hh 32
#define Ww 32
#define Nn 1024   // H*W
#define IBLK 64   // row-blocks per batch in k_row2 (Nn / ROWS_PER_BLK)

// ---------------- scratch (static device globals: allowed) ----------------
__device__ float g_alpha[Bb * Nn];
__device__ float g_beta [Bb * Nn];
__device__ float g_gamma[Bb * Nn];
__device__ float g_part [(size_t)IBLK * Bb * Nn];         // per-block partial column sums
__device__ float g_cinv [Bb * Nn];                        // 1 / csum
__device__ __nv_bfloat16 g_Ahi[(size_t)Bb * Nn * Nn];     // e = exp(-s), split
__device__ __nv_bfloat16 g_Alo[(size_t)Bb * Nn * Nn];
__device__ __nv_bfloat16 g_fhi[(size_t)Bb * Cc * Nn];     // f_src / csum, split
__device__ __nv_bfloat16 g_flo[(size_t)Bb * Cc * Nn];

// ======================= generic-PTX helpers ===============================
__device__ __forceinline__ uint32_t smem_to_u32(const void* p) {
    uint32_t a;
    asm("{ .reg .u64 t; cvta.to.shared.u64 t, %1; cvt.u32.u64 %0, t; }" : "=r"(a) : "l"(p));
    return a;
}
__device__ __forceinline__ void cp16(uint32_t s, const void* g) {
    asm volatile("cp.async.cg.shared.global [%0], [%1], 16;" :: "r"(s), "l"(g));
}
#define CP_COMMIT() asm volatile("cp.async.commit_group;" ::: "memory")
#define CP_WAIT(n)  asm volatile("cp.async.wait_group %0;" :: "n"(n) : "memory")

__device__ __forceinline__ void ldsm_x4(uint32_t* r, uint32_t addr) {
    asm volatile("ldmatrix.sync.aligned.m8n8.x4.shared.b16 {%0,%1,%2,%3}, [%4];"
                 : "=r"(r[0]), "=r"(r[1]), "=r"(r[2]), "=r"(r[3]) : "r"(addr));
}
__device__ __forceinline__ void mma16816(float* c, const uint32_t* a, const uint32_t* b) {
    asm volatile(
        "mma.sync.aligned.m16n8k16.row.col.f32.bf16.bf16.f32 "
        "{%0,%1,%2,%3}, {%4,%5,%6,%7}, {%8,%9}, {%0,%1,%2,%3};"
        : "+f"(c[0]), "+f"(c[1]), "+f"(c[2]), "+f"(c[3])
        : "r"(a[0]), "r"(a[1]), "r"(a[2]), "r"(a[3]), "r"(b[0]), "r"(b[1]));
}

// ---------------- kernel 1: fundamental matrix + per-line coefficients ----
__global__ void k_coef(const float* __restrict__ K1, const float* __restrict__ K2,
                       const float* __restrict__ R,  const float* __restrict__ T)
{
    int b = blockIdx.x;
    __shared__ float F[9];
    if (threadIdx.x == 0) {
        const float* k1 = K1 + b * 9;
        const float* k2 = K2 + b * 9;
        const float* r  = R  + b * 9;
        const float* tv = T  + b * 3;
        float t0 = tv[0], t1 = tv[1], t2 = tv[2];
        float E[9];
        #pragma unroll
        for (int c = 0; c < 3; c++) {
            float r0 = r[0 * 3 + c], r1 = r[1 * 3 + c], r2 = r[2 * 3 + c];
            E[0 * 3 + c] = -t2 * r1 + t1 * r2;
            E[1 * 3 + c] =  t2 * r0 - t0 * r2;
            E[2 * 3 + c] = -t1 * r0 + t0 * r1;
        }
        float fx2 = k2[0], fy2 = k2[4], cx2 = k2[2], cy2 = k2[5];
        float M[9];
        #pragma unroll
        for (int c = 0; c < 3; c++) {
            M[0 * 3 + c] = E[0 * 3 + c] / fx2;
            M[1 * 3 + c] = E[1 * 3 + c] / fy2;
            M[2 * 3 + c] = -cx2 / fx2 * E[0 * 3 + c] - cy2 / fy2 * E[1 * 3 + c] + E[2 * 3 + c];
        }
        float fx1 = k1[0], fy1 = k1[4], cx1 = k1[2], cy1 = k1[5];
        #pragma unroll
        for (int rr = 0; rr < 3; rr++) {
            float m0 = M[rr * 3 + 0], m1 = M[rr * 3 + 1], m2 = M[rr * 3 + 2];
            F[rr * 3 + 0] = m0 / fx1;
            F[rr * 3 + 1] = m1 / fy1;
            F[rr * 3 + 2] = -cx1 / fx1 * m0 - cy1 / fy1 * m1 + m2;
        }
    }
    __syncthreads();
    for (int j = threadIdx.x; j < Nn; j += blockDim.x) {
        float x = (float)(j / Ww);
        float y = (float)(j % Ww);
        float l0 = F[0] * x + F[1] * y + F[2];
        float l1 = F[3] * x + F[4] * y + F[5];
        float l2 = F[6] * x + F[7] * y + F[8];
        float ap = l0 / l2;
        float bp = l1 / l2;
        float rn = rsqrtf(ap * ap + bp * bp);
        g_alpha[b * Nn + j] = ap * rn;
        g_beta [b * Nn + j] = bp * rn;
        g_gamma[b * Nn + j] = rn;
    }
}

// ---------------- kernel 2: fused row-softmax -> e = exp(-s) -> split -----
// Block handles 16 rows. For each row i: v = 5*d_epi, row-softmax s,
// e = exp(-s) (column-softmax shift 0 is safe since s in (0,1]);
// write split(e) to Ahi/Alo; write this block's column-sum slice to g_part.
#define ROWS_PER_BLK 16
__global__ void __launch_bounds__(256) k_row2()
{
    int b  = blockIdx.y;
    int ib = blockIdx.x;
    int i0 = ib * ROWS_PER_BLK;
    const float* al = g_alpha + b * Nn;
    const float* be = g_beta  + b * Nn;
    const float* ga = g_gamma + b * Nn;
    __nv_bfloat16* Ah = g_Ahi + (size_t)b * Nn * Nn;
    __nv_bfloat16* Al = g_Alo + (size_t)b * Nn * Nn;

    __shared__ float redm[8];
    __shared__ float redz[8];

    // per-thread line coefficients (4 columns each, reused across 16 rows)
    float A4[4], B4[4], G4[4];
    float cacc[4];
    #pragma unroll
    for (int k = 0; k < 4; k++) {
        int j = threadIdx.x + k * 256;
        A4[k] = al[j]; B4[k] = be[j]; G4[k] = ga[j];
        cacc[k] = 0.0f;
    }

    for (int r = 0; r < ROWS_PER_BLK; r++) {
        int i = i0 + r;
        float x = (float)(i / Ww);
        float y = (float)(i % Ww);
        float v[4];
        float m = -1e30f;
        #pragma unroll
        for (int k = 0; k < 4; k++) {
            v[k] = 5.0f * fabsf(fmaf(A4[k], x, fmaf(B4[k], y, G4[k])));
            m = fmaxf(m, v[k]);
        }
        #pragma unroll
        for (int o = 16; o; o >>= 1) m = fmaxf(m, __shfl_xor_sync(0xffffffffu, m, o));
        if ((threadIdx.x & 31) == 0) redm[threadIdx.x >> 5] = m;
        __syncthreads();
        float bm = redm[0];
        #pragma unroll
        for (int w = 1; w < 8; w++) bm = fmaxf(bm, redm[w]);

        float e1[4];
        float z = 0.0f;
        #pragma unroll
        for (int k = 0; k < 4; k++) { e1[k] = __expf(v[k] - bm); z += e1[k]; }
        #pragma unroll
        for (int o = 16; o; o >>= 1) z += __shfl_xor_sync(0xffffffffu, z, o);
        if ((threadIdx.x & 31) == 0) redz[threadIdx.x >> 5] = z;
        __syncthreads();
        float bz = 0.0f;
        #pragma unroll
        for (int w = 0; w < 8; w++) bz += redz[w];
        float inv = 1.0f / bz;

        size_t rowoff = (size_t)i * Nn;   // FIX: batch offset lives in Ah/Al pointers
        #pragma unroll
        for (int k = 0; k < 4; k++) {
            float s = e1[k] * inv;               // row-softmax value in (0,1]
            float e = __expf(-s);                // column-softmax numerator (shift 0)
            cacc[k] += e;
            __nv_bfloat16 h = __float2bfloat16(e);
            float lo = e - __bfloat162float(h);
            int j = threadIdx.x + k * 256;
            Ah[rowoff + j] = h;
            Al[rowoff + j] = __float2bfloat16(lo);
        }
    }

    // deterministic partial sums: slice (b, ib)
    size_t poff = ((size_t)(b * IBLK + ib)) * Nn;
    #pragma unroll
    for (int k = 0; k < 4; k++)
        g_part[poff + threadIdx.x + k * 256] = cacc[k];
}

// ---------------- kernel 2b: cinv = 1 / sum_ib part ------------------------
__global__ void k_cinv()
{
    int i = blockIdx.x * blockDim.x + threadIdx.x;
    if (i >= Bb * Nn) return;
    int b = i / Nn, j = i % Nn;
    float s = 0.0f;
    #pragma unroll 8
    for (int ib = 0; ib < IBLK; ib++)
        s += g_part[((size_t)(b * IBLK + ib)) * Nn + j];
    g_cinv[i] = 1.0f / s;
}

// ---------------- kernel 3: split f_src/csum into bf16 hi/lo ---------------
__global__ void k_conv_f(const float* __restrict__ f)
{
    size_t n4 = (size_t)Bb * Cc * Nn / 4;
    for (size_t i = (size_t)blockIdx.x * blockDim.x + threadIdx.x; i < n4;
         i += (size_t)gridDim.x * blockDim.x) {
        float4 v = ((const float4*)f)[i];
        size_t b  = i / ((size_t)Cc * Nn / 4);
        int    j4 = (int)(i % (Nn / 4));
        const float* cv = g_cinv + b * Nn + j4 * 4;   // scalar loads (alignment-safe)
        v.x *= cv[0]; v.y *= cv[1]; v.z *= cv[2]; v.w *= cv[3];
        __nv_bfloat16 h0 = __float2bfloat16(v.x);
        __nv_bfloat16 h1 = __float2bfloat16(v.y);
        __nv_bfloat16 h2 = __float2bfloat16(v.z);
        __nv_bfloat16 h3 = __float2bfloat16(v.w);
        __nv_bfloat16 l0 = __float2bfloat16(v.x - __bfloat162float(h0));
        __nv_bfloat16 l1 = __float2bfloat16(v.y - __bfloat162float(h1));
        __nv_bfloat16 l2 = __float2bfloat16(v.z - __bfloat162float(h2));
        __nv_bfloat16 l3 = __float2bfloat16(v.w - __bfloat162float(h3));
        uint2 ph, pl;
        ph.x = (uint32_t)__bfloat16_as_ushort(h0) | ((uint32_t)__bfloat16_as_ushort(h1) << 16);
        ph.y = (uint32_t)__bfloat16_as_ushort(h2) | ((uint32_t)__bfloat16_as_ushort(h3) << 16);
        pl.x = (uint32_t)__bfloat16_as_ushort(l0) | ((uint32_t)__bfloat16_as_ushort(l1) << 16);
        pl.y = (uint32_t)__bfloat16_as_ushort(l2) | ((uint32_t)__bfloat16_as_ushort(l3) << 16);
        *(uint2*)(g_fhi + 4 * i) = ph;
        *(uint2*)(g_flo + 4 * i) = pl;
    }
}

// ---------------- kernel 4: mma.sync bf16 GEMM out = A @ f^T (3-term) -----
// EXACT R6 structure (proven): double-buffered cp.async, 128KB SMEM.
#define TILE_B   16384          // one 128x64 bf16 tile (swizzled, 128B rows)
#define STAGE_B  (4 * TILE_B)   // Ahi, Alo, Bhi, Blo
#define GEMM_SMEM (2 * STAGE_B) // 131072

__global__ void __launch_bounds__(256, 1) k_gemm_mma(float* __restrict__ out)
{
    extern __shared__ char smem[];
    const uint32_t sb = smem_to_u32(smem);
    const int tid  = threadIdx.x;
    const int wid  = tid >> 5;
    const int lane = tid & 31;
    const int b    = blockIdx.z;
    const int n0   = blockIdx.x * 128;   // c tile
    const int m0   = blockIdx.y * 128;   // i tile

    const __nv_bfloat16* Ah = g_Ahi + (size_t)b * Nn * Nn;
    const __nv_bfloat16* Al = g_Alo + (size_t)b * Nn * Nn;
    const __nv_bfloat16* Fh = g_fhi + (size_t)b * Cc * Nn;
    const __nv_bfloat16* Fl = g_flo + (size_t)b * Cc * Nn;

    // producer chunk mapping: 1024 16B chunks per tile, 4 per thread
    uint32_t p_soff[4];
    uint32_t p_row[4];
    #pragma unroll
    for (int q = 0; q < 4; q++) {
        int id  = tid + q * 256;
        int row = id >> 3;
        int c   = id & 7;
        p_row[q]  = row;
        p_soff[q] = (uint32_t)(row * 128 + ((16 * c) ^ ((row & 7) << 4)));
    }

    // MMA thread geometry
    const int warp_m = wid & 1;        // 0..1
    const int warp_n = wid >> 1;       // 0..3
    const int g  = lane >> 3;          // ldmatrix address group 0..3
    const int r  = lane & 7;
    uint32_t arow[4], brow[2];
    #pragma unroll
    for (int mt = 0; mt < 4; mt++)
        arow[mt] = (uint32_t)((warp_m * 64 + mt * 16 + (g & 1) * 8 + r) * 128);
    #pragma unroll
    for (int p = 0; p < 2; p++)
        brow[p] = (uint32_t)((warp_n * 32 + p * 16 + (g >> 1) * 8 + r) * 128);
    const uint32_t ka_half = (uint32_t)((g >> 1) << 4);
    const uint32_t kb_half = (uint32_t)((g & 1) << 4);
    const uint32_t rx = (uint32_t)(r << 4);

    float acc[4][4][4];
    #pragma unroll
    for (int mt = 0; mt < 4; mt++)
        #pragma unroll
        for (int nt = 0; nt < 4; nt++)
            #pragma unroll
            for (int q = 0; q < 4; q++) acc[mt][nt][q] = 0.0f;

    auto issue_load = [&](int buf, int s) {
        uint32_t base = sb + (uint32_t)buf * STAGE_B;
        int k0 = s * 64;
        #pragma unroll
        for (int q = 0; q < 4; q++) {
            uint32_t row = p_row[q];
            int gk = k0 + ((tid + q * 256) & 7) * 8;
            size_t gA = (size_t)(m0 + row) * Nn + gk;
            size_t gB = (size_t)(n0 + row) * Nn + gk;
            cp16(base + p_soff[q],               Ah + gA);
            cp16(base + TILE_B     + p_soff[q],  Al + gA);
            cp16(base + 2 * TILE_B + p_soff[q],  Fh + gB);
            cp16(base + 3 * TILE_B + p_soff[q],  Fl + gB);
        }
    };

    issue_load(0, 0);
    CP_COMMIT();

    int buf = 0;
    for (int s = 0; s < Nn / 64; s++) {
        if (s + 1 < Nn / 64) {
            issue_load(buf ^ 1, s + 1);
            CP_COMMIT();
            CP_WAIT(1);
        } else {
            CP_WAIT(0);
        }
        __syncthreads();

        uint32_t bA_hi = sb + (uint32_t)buf * STAGE_B;
        uint32_t bA_lo = bA_hi + TILE_B;
        uint32_t bB_hi = bA_hi + 2 * TILE_B;
        uint32_t bB_lo = bA_hi + 3 * TILE_B;

        #pragma unroll
        for (int kk = 0; kk < 4; kk++) {
            uint32_t ka = ((uint32_t)(kk * 32) + ka_half) ^ rx;
            uint32_t kb = ((uint32_t)(kk * 32) + kb_half) ^ rx;
            uint32_t ahi[4][4], alo[4][4];
            #pragma unroll
            for (int mt = 0; mt < 4; mt++) {
                ldsm_x4(ahi[mt], bA_hi + arow[mt] + ka);
                ldsm_x4(alo[mt], bA_lo + arow[mt] + ka);
            }
            uint32_t bhi[2][4], blo[2][4];
            #pragma unroll
            for (int p = 0; p < 2; p++) {
                ldsm_x4(bhi[p], bB_hi + brow[p] + kb);
                ldsm_x4(blo[p], bB_lo + brow[p] + kb);
            }
            #pragma unroll
            for (int mt = 0; mt < 4; mt++) {
                #pragma unroll
                for (int nt = 0; nt < 4; nt++) {
                    const uint32_t* bh = &bhi[nt >> 1][(nt & 1) * 2];
                    const uint32_t* bl = &blo[nt >> 1][(nt & 1) * 2];
                    mma16816(acc[mt][nt], ahi[mt], bh);
                    mma16816(acc[mt][nt], ahi[mt], bl);
                    mma16816(acc[mt][nt], alo[mt], bh);
                }
            }
        }
        __syncthreads();
        buf ^= 1;
    }

    // ---- epilogue: acc -> out[b, i, c] (out stride Cc) ----
    float* Og = out + (size_t)b * Nn * Cc;
    const int rbase = m0 + warp_m * 64 + (lane >> 2);
    const int cbase = n0 + warp_n * 32 + (lane & 3) * 2;
    #pragma unroll
    for (int mt = 0; mt < 4; mt++) {
        #pragma unroll
        for (int nt = 0; nt < 4; nt++) {
            int row = rbase + mt * 16;
            int col = cbase + nt * 8;
            float2 v0 = make_float2(acc[mt][nt][0], acc[mt][nt][1]);
            float2 v1 = make_float2(acc[mt][nt][2], acc[mt][nt][3]);
            *(float2*)(Og + (size_t)row * Cc + col)       = v0;
            *(float2*)(Og + (size_t)(row + 8) * Cc + col) = v1;
        }
    }
}

// ---------------- entry point ---------------------------------------------
extern "C" void kernel_launch(void* const* d_in, const int* in_sizes, int n_in,
                              void* d_out, int out_size)
{
    // metadata order: f_tar(0, unused), f_src(1), K1(2), K2(3), R(4), t(5)
    const float* f_src = (const float*)d_in[1];
    const float* K1    = (const float*)d_in[2];
    const float* K2    = (const float*)d_in[3];
    const float* R     = (const float*)d_in[4];
    const float* T     = (const float*)d_in[5];
    float* out = (float*)d_out;

    cudaFuncSetAttribute(k_gemm_mma, cudaFuncAttributeMaxDynamicSharedMemorySize, GEMM_SMEM);

    k_coef<<<Bb, 256>>>(K1, K2, R, T);
    k_row2<<<dim3(IBLK, Bb), 256>>>();
    k_cinv<<<(Bb * Nn + 255) / 256, 256>>>();
    k_conv_f<<<1024, 256>>>(f_src);
    k_gemm_mma<<<dim3(Cc / 128, Nn / 128, Bb), 256, GEMM_SMEM>>>(out);
}

// round 10
// speedup vs baseline: 3.3883x; 1.3770x over previous
#include <cuda_runtime.h>
#include <cuda_fp16.h>
#include <cstdint>
#include <math.h>

// Problem constants
#define Bb 8
#define Cc 1152
#define Hh 32
#define Ww 32
#define Nn 1024   // H*W
#define IBLK 64   // row-blocks per batch in k_row2 (Nn / ROWS_PER_BLK)

// ---------------- scratch (static device globals: allowed) ----------------
__device__ float g_alpha[Bb * Nn];
__device__ float g_beta [Bb * Nn];
__device__ float g_gamma[Bb * Nn];
__device__ float g_part [(size_t)IBLK * Bb * Nn];         // per-block partial column sums
__device__ float g_cinv [Bb * Nn];                        // 1 / csum
__device__ float g_colsum[Bb * Cc];                       // colsum_c = sum_j F[c,j] (fp32 exact)
__device__ __half g_Uhi[(size_t)Bb * Nn * Nn];            // u = 1 - exp(-s), fp16 split
__device__ __half g_Ulo[(size_t)Bb * Nn * Nn];
__device__ __half g_F  [(size_t)Bb * Cc * Nn];            // F = f_src / csum, single fp16

// ======================= generic-PTX helpers ===============================
__device__ __forceinline__ uint32_t smem_to_u32(const void* p) {
    uint32_t a;
    asm("{ .reg .u64 t; cvta.to.shared.u64 t, %1; cvt.u32.u64 %0, t; }" : "=r"(a) : "l"(p));
    return a;
}
__device__ __forceinline__ void cp16(uint32_t s, const void* g) {
    asm volatile("cp.async.cg.shared.global [%0], [%1], 16;" :: "r"(s), "l"(g));
}
#define CP_COMMIT() asm volatile("cp.async.commit_group;" ::: "memory")
#define CP_WAIT(n)  asm volatile("cp.async.wait_group %0;" :: "n"(n) : "memory")

__device__ __forceinline__ void ldsm_x4(uint32_t* r, uint32_t addr) {
    asm volatile("ldmatrix.sync.aligned.m8n8.x4.shared.b16 {%0,%1,%2,%3}, [%4];"
                 : "=r"(r[0]), "=r"(r[1]), "=r"(r[2]), "=r"(r[3]) : "r"(addr));
}
__device__ __forceinline__ void mma16816h(float* c, const uint32_t* a, const uint32_t* b) {
    asm volatile(
        "mma.sync.aligned.m16n8k16.row.col.f32.f16.f16.f32 "
        "{%0,%1,%2,%3}, {%4,%5,%6,%7}, {%8,%9}, {%0,%1,%2,%3};"
        : "+f"(c[0]), "+f"(c[1]), "+f"(c[2]), "+f"(c[3])
        : "r"(a[0]), "r"(a[1]), "r"(a[2]), "r"(a[3]), "r"(b[0]), "r"(b[1]));
}

// ---------------- kernel 1: fundamental matrix + per-line coefficients ----
__global__ void k_coef(const float* __restrict__ K1, const float* __restrict__ K2,
                       const float* __restrict__ R,  const float* __restrict__ T)
{
    int b = blockIdx.x;
    __shared__ float F[9];
    if (threadIdx.x == 0) {
        const float* k1 = K1 + b * 9;
        const float* k2 = K2 + b * 9;
        const float* r  = R  + b * 9;
        const float* tv = T  + b * 3;
        float t0 = tv[0], t1 = tv[1], t2 = tv[2];
        float E[9];
        #pragma unroll
        for (int c = 0; c < 3; c++) {
            float r0 = r[0 * 3 + c], r1 = r[1 * 3 + c], r2 = r[2 * 3 + c];
            E[0 * 3 + c] = -t2 * r1 + t1 * r2;
            E[1 * 3 + c] =  t2 * r0 - t0 * r2;
            E[2 * 3 + c] = -t1 * r0 + t0 * r1;
        }
        float fx2 = k2[0], fy2 = k2[4], cx2 = k2[2], cy2 = k2[5];
        float M[9];
        #pragma unroll
        for (int c = 0; c < 3; c++) {
            M[0 * 3 + c] = E[0 * 3 + c] / fx2;
            M[1 * 3 + c] = E[1 * 3 + c] / fy2;
            M[2 * 3 + c] = -cx2 / fx2 * E[0 * 3 + c] - cy2 / fy2 * E[1 * 3 + c] + E[2 * 3 + c];
        }
        float fx1 = k1[0], fy1 = k1[4], cx1 = k1[2], cy1 = k1[5];
        #pragma unroll
        for (int rr = 0; rr < 3; rr++) {
            float m0 = M[rr * 3 + 0], m1 = M[rr * 3 + 1], m2 = M[rr * 3 + 2];
            F[rr * 3 + 0] = m0 / fx1;
            F[rr * 3 + 1] = m1 / fy1;
            F[rr * 3 + 2] = -cx1 / fx1 * m0 - cy1 / fy1 * m1 + m2;
        }
    }
    __syncthreads();
    for (int j = threadIdx.x; j < Nn; j += blockDim.x) {
        float x = (float)(j / Ww);
        float y = (float)(j % Ww);
        float l0 = F[0] * x + F[1] * y + F[2];
        float l1 = F[3] * x + F[4] * y + F[5];
        float l2 = F[6] * x + F[7] * y + F[8];
        float ap = l0 / l2;
        float bp = l1 / l2;
        float rn = rsqrtf(ap * ap + bp * bp);
        g_alpha[b * Nn + j] = ap * rn;
        g_beta [b * Nn + j] = bp * rn;
        g_gamma[b * Nn + j] = rn;
    }
}

// ---------------- kernel 2: fused row-softmax -> u = 1-exp(-s) split -----
// Block handles 16 rows. For row i: v = 5*d_epi, row-softmax s, e = exp(-s);
// u = 1-e split into fp16 hi/lo (GEMM operand); e accumulated for csum.
#define ROWS_PER_BLK 16
__global__ void __launch_bounds__(256) k_row2()
{
    int b  = blockIdx.y;
    int ib = blockIdx.x;
    int i0 = ib * ROWS_PER_BLK;
    const float* al = g_alpha + b * Nn;
    const float* be = g_beta  + b * Nn;
    const float* ga = g_gamma + b * Nn;
    __half* Uh = g_Uhi + (size_t)b * Nn * Nn;
    __half* Ul = g_Ulo + (size_t)b * Nn * Nn;

    __shared__ float redm[8];
    __shared__ float redz[8];

    float A4[4], B4[4], G4[4];
    float cacc[4];
    #pragma unroll
    for (int k = 0; k < 4; k++) {
        int j = threadIdx.x + k * 256;
        A4[k] = al[j]; B4[k] = be[j]; G4[k] = ga[j];
        cacc[k] = 0.0f;
    }

    for (int r = 0; r < ROWS_PER_BLK; r++) {
        int i = i0 + r;
        float x = (float)(i / Ww);
        float y = (float)(i % Ww);
        float v[4];
        float m = -1e30f;
        #pragma unroll
        for (int k = 0; k < 4; k++) {
            v[k] = 5.0f * fabsf(fmaf(A4[k], x, fmaf(B4[k], y, G4[k])));
            m = fmaxf(m, v[k]);
        }
        #pragma unroll
        for (int o = 16; o; o >>= 1) m = fmaxf(m, __shfl_xor_sync(0xffffffffu, m, o));
        if ((threadIdx.x & 31) == 0) redm[threadIdx.x >> 5] = m;
        __syncthreads();
        float bm = redm[0];
        #pragma unroll
        for (int w = 1; w < 8; w++) bm = fmaxf(bm, redm[w]);

        float e1[4];
        float z = 0.0f;
        #pragma unroll
        for (int k = 0; k < 4; k++) { e1[k] = __expf(v[k] - bm); z += e1[k]; }
        #pragma unroll
        for (int o = 16; o; o >>= 1) z += __shfl_xor_sync(0xffffffffu, z, o);
        if ((threadIdx.x & 31) == 0) redz[threadIdx.x >> 5] = z;
        __syncthreads();
        float bz = 0.0f;
        #pragma unroll
        for (int w = 0; w < 8; w++) bz += redz[w];
        float inv = 1.0f / bz;

        size_t rowoff = (size_t)i * Nn;   // batch offset lives in Uh/Ul pointers
        #pragma unroll
        for (int k = 0; k < 4; k++) {
            float s = e1[k] * inv;               // row-softmax value in (0,1]
            float e = __expf(-s);                // column-softmax numerator (shift 0)
            cacc[k] += e;
            float u = 1.0f - e;                  // GEMM operand: out = colsum - U@F^T
            __half h = __float2half_rn(u);
            float lo = u - __half2float(h);
            int j = threadIdx.x + k * 256;
            Uh[rowoff + j] = h;
            Ul[rowoff + j] = __float2half_rn(lo);
        }
    }

    size_t poff = ((size_t)(b * IBLK + ib)) * Nn;
    #pragma unroll
    for (int k = 0; k < 4; k++)
        g_part[poff + threadIdx.x + k * 256] = cacc[k];
}

// ---------------- kernel 2b: cinv = 1 / sum_ib part ------------------------
__global__ void k_cinv()
{
    int i = blockIdx.x * blockDim.x + threadIdx.x;
    if (i >= Bb * Nn) return;
    int b = i / Nn, j = i % Nn;
    float s = 0.0f;
    #pragma unroll 8
    for (int ib = 0; ib < IBLK; ib++)
        s += g_part[((size_t)(b * IBLK + ib)) * Nn + j];
    g_cinv[i] = 1.0f / s;
}

// ---------------- kernel 3: F = f/csum -> fp16; colsum_c = sum_j F (fp32) --
// Block handles 4 consecutive c-rows of one batch. Thread t owns float4 #t of
// each 1024-element row; cinv cached in regs; deterministic block reduction.
__global__ void __launch_bounds__(256) k_conv_f(const float* __restrict__ f)
{
    int b  = blockIdx.y;
    int c0 = blockIdx.x * 4;
    int tid = threadIdx.x;
    const float* ci = g_cinv + b * Nn + tid * 4;
    float cv0 = ci[0], cv1 = ci[1], cv2 = ci[2], cv3 = ci[3];
    __shared__ float red[8];

    #pragma unroll
    for (int r = 0; r < 4; r++) {
        int c = c0 + r;
        size_t rowbase = ((size_t)(b * Cc + c)) * Nn;
        float4 v = *(const float4*)(f + rowbase + tid * 4);
        v.x *= cv0; v.y *= cv1; v.z *= cv2; v.w *= cv3;

        uint32_t w0 = (uint32_t)__half_as_ushort(__float2half_rn(v.x)) |
                      ((uint32_t)__half_as_ushort(__float2half_rn(v.y)) << 16);
        uint32_t w1 = (uint32_t)__half_as_ushort(__float2half_rn(v.z)) |
                      ((uint32_t)__half_as_ushort(__float2half_rn(v.w)) << 16);
        uint2 pk; pk.x = w0; pk.y = w1;
        *(uint2*)(g_F + rowbase + tid * 4) = pk;

        float sm = (v.x + v.y) + (v.z + v.w);   // fp32 colsum contribution
        #pragma unroll
        for (int o = 16; o; o >>= 1) sm += __shfl_xor_sync(0xffffffffu, sm, o);
        if ((tid & 31) == 0) red[tid >> 5] = sm;
        __syncthreads();
        if (tid == 0) {
            float t = 0.0f;
            #pragma unroll
            for (int w = 0; w < 8; w++) t += red[w];
            g_colsum[b * Cc + c] = t;
        }
        __syncthreads();
    }
}

// ---------------- kernel 4: fp16 mma GEMM, out = colsum - U @ F^T ---------
// Tile M=128 (i), N=128 (c), K in 16 stages of 64. Stage: Uhi/Ulo/F tiles of
// 128x64 fp16 (16KB each, XOR swizzle), double-buffered = 96KB SMEM.
// 2 MMA terms per tile: Uh*F + Ul*F (U split carries 22-bit precision).
#define TILE_B   16384          // one 128x64 fp16 tile (swizzled, 128B rows)
#define STAGE_B  (3 * TILE_B)   // Uhi, Ulo, F
#define GEMM_SMEM (2 * STAGE_B) // 98304

__global__ void __launch_bounds__(256, 2) k_gemm_mma(float* __restrict__ out)
{
    extern __shared__ char smem[];
    const uint32_t sb = smem_to_u32(smem);
    const int tid  = threadIdx.x;
    const int wid  = tid >> 5;
    const int lane = tid & 31;
    const int b    = blockIdx.z;
    const int n0   = blockIdx.x * 128;   // c tile
    const int m0   = blockIdx.y * 128;   // i tile

    const __half* Uh = g_Uhi + (size_t)b * Nn * Nn;
    const __half* Ul = g_Ulo + (size_t)b * Nn * Nn;
    const __half* Fp = g_F   + (size_t)b * Cc * Nn;

    // producer chunk mapping: 1024 16B chunks per tile, 4 per thread
    uint32_t p_soff[4];
    uint32_t p_row[4];
    #pragma unroll
    for (int q = 0; q < 4; q++) {
        int id  = tid + q * 256;
        int row = id >> 3;
        int c   = id & 7;
        p_row[q]  = row;
        p_soff[q] = (uint32_t)(row * 128 + ((16 * c) ^ ((row & 7) << 4)));
    }

    // MMA thread geometry
    const int warp_m = wid & 1;        // 0..1
    const int warp_n = wid >> 1;       // 0..3
    const int g  = lane >> 3;          // ldmatrix address group 0..3
    const int r  = lane & 7;
    uint32_t arow[4], brow[2];
    #pragma unroll
    for (int mt = 0; mt < 4; mt++)
        arow[mt] = (uint32_t)((warp_m * 64 + mt * 16 + (g & 1) * 8 + r) * 128);
    #pragma unroll
    for (int p = 0; p < 2; p++)
        brow[p] = (uint32_t)((warp_n * 32 + p * 16 + (g >> 1) * 8 + r) * 128);
    const uint32_t ka_half = (uint32_t)((g >> 1) << 4);
    const uint32_t kb_half = (uint32_t)((g & 1) << 4);
    const uint32_t rx = (uint32_t)(r << 4);

    float acc[4][4][4];
    #pragma unroll
    for (int mt = 0; mt < 4; mt++)
        #pragma unroll
        for (int nt = 0; nt < 4; nt++)
            #pragma unroll
            for (int q = 0; q < 4; q++) acc[mt][nt][q] = 0.0f;

    auto issue_load = [&](int buf, int s) {
        uint32_t base = sb + (uint32_t)buf * STAGE_B;
        int k0 = s * 64;
        #pragma unroll
        for (int q = 0; q < 4; q++) {
            uint32_t row = p_row[q];
            int gk = k0 + ((tid + q * 256) & 7) * 8;
            size_t gA = (size_t)(m0 + row) * Nn + gk;
            size_t gB = (size_t)(n0 + row) * Nn + gk;
            cp16(base + p_soff[q],               Uh + gA);
            cp16(base + TILE_B     + p_soff[q],  Ul + gA);
            cp16(base + 2 * TILE_B + p_soff[q],  Fp + gB);
        }
    };

    issue_load(0, 0);
    CP_COMMIT();

    int buf = 0;
    for (int s = 0; s < Nn / 64; s++) {
        if (s + 1 < Nn / 64) {
            issue_load(buf ^ 1, s + 1);
            CP_COMMIT();
            CP_WAIT(1);
        } else {
            CP_WAIT(0);
        }
        __syncthreads();

        uint32_t bU_hi = sb + (uint32_t)buf * STAGE_B;
        uint32_t bU_lo = bU_hi + TILE_B;
        uint32_t bF    = bU_hi + 2 * TILE_B;

        #pragma unroll
        for (int kk = 0; kk < 4; kk++) {
            uint32_t ka = ((uint32_t)(kk * 32) + ka_half) ^ rx;
            uint32_t kb = ((uint32_t)(kk * 32) + kb_half) ^ rx;
            uint32_t uhi[4][4], ulo[4][4];
            #pragma unroll
            for (int mt = 0; mt < 4; mt++) {
                ldsm_x4(uhi[mt], bU_hi + arow[mt] + ka);
                ldsm_x4(ulo[mt], bU_lo + arow[mt] + ka);
            }
            uint32_t fr[2][4];
            #pragma unroll
            for (int p = 0; p < 2; p++)
                ldsm_x4(fr[p], bF + brow[p] + kb);
            #pragma unroll
            for (int mt = 0; mt < 4; mt++) {
                #pragma unroll
                for (int nt = 0; nt < 4; nt++) {
                    const uint32_t* fb = &fr[nt >> 1][(nt & 1) * 2];
                    mma16816h(acc[mt][nt], uhi[mt], fb);
                    mma16816h(acc[mt][nt], ulo[mt], fb);
                }
            }
        }
        __syncthreads();
        buf ^= 1;
    }

    // ---- epilogue: out[i,c] = colsum[c] - acc ----
    float* Og = out + (size_t)b * Nn * Cc;
    const float* cs = g_colsum + b * Cc;
    const int rbase = m0 + warp_m * 64 + (lane >> 2);
    const int cbase = n0 + warp_n * 32 + (lane & 3) * 2;
    #pragma unroll
    for (int nt = 0; nt < 4; nt++) {
        int col = cbase + nt * 8;
        float cs0 = cs[col];
        float cs1 = cs[col + 1];
        #pragma unroll
        for (int mt = 0; mt < 4; mt++) {
            int row = rbase + mt * 16;
            float2 v0 = make_float2(cs0 - acc[mt][nt][0], cs1 - acc[mt][nt][1]);
            float2 v1 = make_float2(cs0 - acc[mt][nt][2], cs1 - acc[mt][nt][3]);
            *(float2*)(Og + (size_t)row * Cc + col)       = v0;
            *(float2*)(Og + (size_t)(row + 8) * Cc + col) = v1;
        }
    }
}

// ---------------- entry point ---------------------------------------------
extern "C" void kernel_launch(void* const* d_in, const int* in_sizes, int n_in,
                              void* d_out, int out_size)
{
    // metadata order: f_tar(0, unused), f_src(1), K1(2), K2(3), R(4), t(5)
    const float* f_src = (const float*)d_in[1];
    const float* K1    = (const float*)d_in[2];
    const float* K2    = (const float*)d_in[3];
    const float* R     = (const float*)d_in[4];
    const float* T     = (const float*)d_in[5];
    float* out = (float*)d_out;

    cudaFuncSetAttribute(k_gemm_mma, cudaFuncAttributeMaxDynamicSharedMemorySize, GEMM_SMEM);

    k_coef<<<Bb, 256>>>(K1, K2, R, T);
    k_row2<<<dim3(IBLK, Bb), 256>>>();
    k_cinv<<<(Bb * Nn + 255) / 256, 256>>>();
    k_conv_f<<<dim3(Cc / 4, Bb), 256>>>(f_src);
    k_gemm_mma<<<dim3(Cc / 128, Nn / 128, Bb), 256, GEMM_SMEM>>>(out);
}

// round 11
// speedup vs baseline: 4.9552x; 1.4624x over previous
#include <cuda_runtime.h>
#include <cuda_fp16.h>
#include <cstdint>
#include <math.h>

// Problem constants
#define Bb 8
#define Cc 1152
#define Hh 32
#define Ww 32
#define Nn 1024   // H*W
#define IBLK 64   // row-blocks per batch in k_row2 (Nn / ROWS_PER_BLK)

// ---------------- scratch (static device globals: allowed) ----------------
__device__ float g_alpha[Bb * Nn];
__device__ float g_beta [Bb * Nn];
__device__ float g_gamma[Bb * Nn];
__device__ float g_part [(size_t)IBLK * Bb * Nn];         // per-block partial column sums
__device__ float g_cinv [Bb * Nn];                        // 1 / csum
__device__ float g_colsum[Bb * Cc];                       // colsum_c = sum_j F[c,j] (fp32 exact)
__device__ __half g_U[(size_t)Bb * Nn * Nn];              // u = 1 - exp(-s), fp16
__device__ __half g_F[(size_t)Bb * Cc * Nn];              // F = f_src / csum, fp16

// ======================= generic-PTX helpers ===============================
__device__ __forceinline__ uint32_t smem_to_u32(const void* p) {
    uint32_t a;
    asm("{ .reg .u64 t; cvta.to.shared.u64 t, %1; cvt.u32.u64 %0, t; }" : "=r"(a) : "l"(p));
    return a;
}
__device__ __forceinline__ void cp16(uint32_t s, const void* g) {
    asm volatile("cp.async.cg.shared.global [%0], [%1], 16;" :: "r"(s), "l"(g));
}
#define CP_COMMIT() asm volatile("cp.async.commit_group;" ::: "memory")
#define CP_WAIT(n)  asm volatile("cp.async.wait_group %0;" :: "n"(n) : "memory")

__device__ __forceinline__ void ldsm_x4(uint32_t* r, uint32_t addr) {
    asm volatile("ldmatrix.sync.aligned.m8n8.x4.shared.b16 {%0,%1,%2,%3}, [%4];"
                 : "=r"(r[0]), "=r"(r[1]), "=r"(r[2]), "=r"(r[3]) : "r"(addr));
}
__device__ __forceinline__ void mma16816h(float* c, const uint32_t* a, const uint32_t* b) {
    asm volatile(
        "mma.sync.aligned.m16n8k16.row.col.f32.f16.f16.f32 "
        "{%0,%1,%2,%3}, {%4,%5,%6,%7}, {%8,%9}, {%0,%1,%2,%3};"
        : "+f"(c[0]), "+f"(c[1]), "+f"(c[2]), "+f"(c[3])
        : "r"(a[0]), "r"(a[1]), "r"(a[2]), "r"(a[3]), "r"(b[0]), "r"(b[1]));
}

// ---------------- kernel 1: fundamental matrix + per-line coefficients ----
__global__ void k_coef(const float* __restrict__ K1, const float* __restrict__ K2,
                       const float* __restrict__ R,  const float* __restrict__ T)
{
    int b = blockIdx.x;
    __shared__ float F[9];
    if (threadIdx.x == 0) {
        const float* k1 = K1 + b * 9;
        const float* k2 = K2 + b * 9;
        const float* r  = R  + b * 9;
        const float* tv = T  + b * 3;
        float t0 = tv[0], t1 = tv[1], t2 = tv[2];
        float E[9];
        #pragma unroll
        for (int c = 0; c < 3; c++) {
            float r0 = r[0 * 3 + c], r1 = r[1 * 3 + c], r2 = r[2 * 3 + c];
            E[0 * 3 + c] = -t2 * r1 + t1 * r2;
            E[1 * 3 + c] =  t2 * r0 - t0 * r2;
            E[2 * 3 + c] = -t1 * r0 + t0 * r1;
        }
        float fx2 = k2[0], fy2 = k2[4], cx2 = k2[2], cy2 = k2[5];
        float M[9];
        #pragma unroll
        for (int c = 0; c < 3; c++) {
            M[0 * 3 + c] = E[0 * 3 + c] / fx2;
            M[1 * 3 + c] = E[1 * 3 + c] / fy2;
            M[2 * 3 + c] = -cx2 / fx2 * E[0 * 3 + c] - cy2 / fy2 * E[1 * 3 + c] + E[2 * 3 + c];
        }
        float fx1 = k1[0], fy1 = k1[4], cx1 = k1[2], cy1 = k1[5];
        #pragma unroll
        for (int rr = 0; rr < 3; rr++) {
            float m0 = M[rr * 3 + 0], m1 = M[rr * 3 + 1], m2 = M[rr * 3 + 2];
            F[rr * 3 + 0] = m0 / fx1;
            F[rr * 3 + 1] = m1 / fy1;
            F[rr * 3 + 2] = -cx1 / fx1 * m0 - cy1 / fy1 * m1 + m2;
        }
    }
    __syncthreads();
    for (int j = threadIdx.x; j < Nn; j += blockDim.x) {
        float x = (float)(j / Ww);
        float y = (float)(j % Ww);
        float l0 = F[0] * x + F[1] * y + F[2];
        float l1 = F[3] * x + F[4] * y + F[5];
        float l2 = F[6] * x + F[7] * y + F[8];
        float ap = l0 / l2;
        float bp = l1 / l2;
        float rn = rsqrtf(ap * ap + bp * bp);
        g_alpha[b * Nn + j] = ap * rn;
        g_beta [b * Nn + j] = bp * rn;
        g_gamma[b * Nn + j] = rn;
    }
}

// ---------------- kernel 2: fused row-softmax -> u = 1-exp(-s) fp16 ------
#define ROWS_PER_BLK 16
__global__ void __launch_bounds__(256) k_row2()
{
    int b  = blockIdx.y;
    int ib = blockIdx.x;
    int i0 = ib * ROWS_PER_BLK;
    const float* al = g_alpha + b * Nn;
    const float* be = g_beta  + b * Nn;
    const float* ga = g_gamma + b * Nn;
    __half* Up = g_U + (size_t)b * Nn * Nn;

    __shared__ float redm[8];
    __shared__ float redz[8];

    float A4[4], B4[4], G4[4];
    float cacc[4];
    #pragma unroll
    for (int k = 0; k < 4; k++) {
        int j = threadIdx.x + k * 256;
        A4[k] = al[j]; B4[k] = be[j]; G4[k] = ga[j];
        cacc[k] = 0.0f;
    }

    for (int r = 0; r < ROWS_PER_BLK; r++) {
        int i = i0 + r;
        float x = (float)(i / Ww);
        float y = (float)(i % Ww);
        float v[4];
        float m = -1e30f;
        #pragma unroll
        for (int k = 0; k < 4; k++) {
            v[k] = 5.0f * fabsf(fmaf(A4[k], x, fmaf(B4[k], y, G4[k])));
            m = fmaxf(m, v[k]);
        }
        #pragma unroll
        for (int o = 16; o; o >>= 1) m = fmaxf(m, __shfl_xor_sync(0xffffffffu, m, o));
        if ((threadIdx.x & 31) == 0) redm[threadIdx.x >> 5] = m;
        __syncthreads();
        float bm = redm[0];
        #pragma unroll
        for (int w = 1; w < 8; w++) bm = fmaxf(bm, redm[w]);

        float e1[4];
        float z = 0.0f;
        #pragma unroll
        for (int k = 0; k < 4; k++) { e1[k] = __expf(v[k] - bm); z += e1[k]; }
        #pragma unroll
        for (int o = 16; o; o >>= 1) z += __shfl_xor_sync(0xffffffffu, z, o);
        if ((threadIdx.x & 31) == 0) redz[threadIdx.x >> 5] = z;
        __syncthreads();
        float bz = 0.0f;
        #pragma unroll
        for (int w = 0; w < 8; w++) bz += redz[w];
        float inv = 1.0f / bz;

        size_t rowoff = (size_t)i * Nn;   // batch offset lives in Up pointer
        #pragma unroll
        for (int k = 0; k < 4; k++) {
            float s = e1[k] * inv;               // row-softmax value in (0,1]
            float e = __expf(-s);                // column-softmax numerator (shift 0)
            cacc[k] += e;
            float u = 1.0f - e;                  // GEMM operand: out = colsum - U@F^T
            int j = threadIdx.x + k * 256;
            Up[rowoff + j] = __float2half_rn(u);
        }
    }

    size_t poff = ((size_t)(b * IBLK + ib)) * Nn;
    #pragma unroll
    for (int k = 0; k < 4; k++)
        g_part[poff + threadIdx.x + k * 256] = cacc[k];
}

// ---------------- kernel 2b: cinv = 1 / sum_ib part ------------------------
__global__ void k_cinv()
{
    int i = blockIdx.x * blockDim.x + threadIdx.x;
    if (i >= Bb * Nn) return;
    int b = i / Nn, j = i % Nn;
    float s = 0.0f;
    #pragma unroll 8
    for (int ib = 0; ib < IBLK; ib++)
        s += g_part[((size_t)(b * IBLK + ib)) * Nn + j];
    g_cinv[i] = 1.0f / s;
}

// ---------------- kernel 3: F = f/csum -> fp16; colsum_c = sum_j F (fp32) --
__global__ void __launch_bounds__(256) k_conv_f(const float* __restrict__ f)
{
    int b  = blockIdx.y;
    int c0 = blockIdx.x * 4;
    int tid = threadIdx.x;
    const float* ci = g_cinv + b * Nn + tid * 4;
    float cv0 = ci[0], cv1 = ci[1], cv2 = ci[2], cv3 = ci[3];
    __shared__ float red[8];

    #pragma unroll
    for (int r = 0; r < 4; r++) {
        int c = c0 + r;
        size_t rowbase = ((size_t)(b * Cc + c)) * Nn;
        float4 v = *(const float4*)(f + rowbase + tid * 4);
        v.x *= cv0; v.y *= cv1; v.z *= cv2; v.w *= cv3;

        uint32_t w0 = (uint32_t)__half_as_ushort(__float2half_rn(v.x)) |
                      ((uint32_t)__half_as_ushort(__float2half_rn(v.y)) << 16);
        uint32_t w1 = (uint32_t)__half_as_ushort(__float2half_rn(v.z)) |
                      ((uint32_t)__half_as_ushort(__float2half_rn(v.w)) << 16);
        uint2 pk; pk.x = w0; pk.y = w1;
        *(uint2*)(g_F + rowbase + tid * 4) = pk;

        float sm = (v.x + v.y) + (v.z + v.w);   // fp32 colsum contribution
        #pragma unroll
        for (int o = 16; o; o >>= 1) sm += __shfl_xor_sync(0xffffffffu, sm, o);
        if ((tid & 31) == 0) red[tid >> 5] = sm;
        __syncthreads();
        if (tid == 0) {
            float t = 0.0f;
            #pragma unroll
            for (int w = 0; w < 8; w++) t += red[w];
            g_colsum[b * Cc + c] = t;
        }
        __syncthreads();
    }
}

// ---------------- kernel 4: fp16 mma GEMM, out = colsum - U @ F^T ---------
// Tile M=128 (i), N=128 (c), K in 16 stages of 64. Stage: U/F tiles of
// 128x64 fp16 (16KB each, XOR swizzle), double-buffered = 64KB SMEM.
// SINGLE MMA term per tile (fp16 U; error calibrated ~1e-5 in harness metric).
#define TILE_B   16384          // one 128x64 fp16 tile (swizzled, 128B rows)
#define STAGE_B  (2 * TILE_B)   // U, F
#define GEMM_SMEM (2 * STAGE_B) // 65536

__global__ void __launch_bounds__(256, 2) k_gemm_mma(float* __restrict__ out)
{
    extern __shared__ char smem[];
    const uint32_t sb = smem_to_u32(smem);
    const int tid  = threadIdx.x;
    const int wid  = tid >> 5;
    const int lane = tid & 31;
    const int b    = blockIdx.z;
    const int n0   = blockIdx.x * 128;   // c tile
    const int m0   = blockIdx.y * 128;   // i tile

    const __half* Up = g_U + (size_t)b * Nn * Nn;
    const __half* Fp = g_F + (size_t)b * Cc * Nn;

    // producer chunk mapping: 1024 16B chunks per tile, 4 per thread
    uint32_t p_soff[4];
    uint32_t p_row[4];
    #pragma unroll
    for (int q = 0; q < 4; q++) {
        int id  = tid + q * 256;
        int row = id >> 3;
        int c   = id & 7;
        p_row[q]  = row;
        p_soff[q] = (uint32_t)(row * 128 + ((16 * c) ^ ((row & 7) << 4)));
    }

    // MMA thread geometry
    const int warp_m = wid & 1;        // 0..1
    const int warp_n = wid >> 1;       // 0..3
    const int g  = lane >> 3;          // ldmatrix address group 0..3
    const int r  = lane & 7;
    uint32_t arow[4], brow[2];
    #pragma unroll
    for (int mt = 0; mt < 4; mt++)
        arow[mt] = (uint32_t)((warp_m * 64 + mt * 16 + (g & 1) * 8 + r) * 128);
    #pragma unroll
    for (int p = 0; p < 2; p++)
        brow[p] = (uint32_t)((warp_n * 32 + p * 16 + (g >> 1) * 8 + r) * 128);
    const uint32_t ka_half = (uint32_t)((g >> 1) << 4);
    const uint32_t kb_half = (uint32_t)((g & 1) << 4);
    const uint32_t rx = (uint32_t)(r << 4);

    float acc[4][4][4];
    #pragma unroll
    for (int mt = 0; mt < 4; mt++)
        #pragma unroll
        for (int nt = 0; nt < 4; nt++)
            #pragma unroll
            for (int q = 0; q < 4; q++) acc[mt][nt][q] = 0.0f;

    auto issue_load = [&](int buf, int s) {
        uint32_t base = sb + (uint32_t)buf * STAGE_B;
        int k0 = s * 64;
        #pragma unroll
        for (int q = 0; q < 4; q++) {
            uint32_t row = p_row[q];
            int gk = k0 + ((tid + q * 256) & 7) * 8;
            size_t gA = (size_t)(m0 + row) * Nn + gk;
            size_t gB = (size_t)(n0 + row) * Nn + gk;
            cp16(base + p_soff[q],          Up + gA);
            cp16(base + TILE_B + p_soff[q], Fp + gB);
        }
    };

    issue_load(0, 0);
    CP_COMMIT();

    int buf = 0;
    for (int s = 0; s < Nn / 64; s++) {
        if (s + 1 < Nn / 64) {
            issue_load(buf ^ 1, s + 1);
            CP_COMMIT();
            CP_WAIT(1);
        } else {
            CP_WAIT(0);
        }
        __syncthreads();

        uint32_t bU = sb + (uint32_t)buf * STAGE_B;
        uint32_t bF = bU + TILE_B;

        #pragma unroll
        for (int kk = 0; kk < 4; kk++) {
            uint32_t ka = ((uint32_t)(kk * 32) + ka_half) ^ rx;
            uint32_t kb = ((uint32_t)(kk * 32) + kb_half) ^ rx;
            uint32_t ur[4][4];
            #pragma unroll
            for (int mt = 0; mt < 4; mt++)
                ldsm_x4(ur[mt], bU + arow[mt] + ka);
            uint32_t fr[2][4];
            #pragma unroll
            for (int p = 0; p < 2; p++)
                ldsm_x4(fr[p], bF + brow[p] + kb);
            #pragma unroll
            for (int mt = 0; mt < 4; mt++) {
                #pragma unroll
                for (int nt = 0; nt < 4; nt++) {
                    const uint32_t* fb = &fr[nt >> 1][(nt & 1) * 2];
                    mma16816h(acc[mt][nt], ur[mt], fb);
                }
            }
        }
        __syncthreads();
        buf ^= 1;
    }

    // ---- epilogue: out[i,c] = colsum[c] - acc ----
    float* Og = out + (size_t)b * Nn * Cc;
    const float* cs = g_colsum + b * Cc;
    const int rbase = m0 + warp_m * 64 + (lane >> 2);
    const int cbase = n0 + warp_n * 32 + (lane & 3) * 2;
    #pragma unroll
    for (int nt = 0; nt < 4; nt++) {
        int col = cbase + nt * 8;
        float cs0 = cs[col];
        float cs1 = cs[col + 1];
        #pragma unroll
        for (int mt = 0; mt < 4; mt++) {
            int row = rbase + mt * 16;
            float2 v0 = make_float2(cs0 - acc[mt][nt][0], cs1 - acc[mt][nt][1]);
            float2 v1 = make_float2(cs0 - acc[mt][nt][2], cs1 - acc[mt][nt][3]);
            *(float2*)(Og + (size_t)row * Cc + col)       = v0;
            *(float2*)(Og + (size_t)(row + 8) * Cc + col) = v1;
        }
    }
}

// ---------------- entry point ---------------------------------------------
extern "C" void kernel_launch(void* const* d_in, const int* in_sizes, int n_in,
                              void* d_out, int out_size)
{
    // metadata order: f_tar(0, unused), f_src(1), K1(2), K2(3), R(4), t(5)
    const float* f_src = (const float*)d_in[1];
    const float* K1    = (const float*)d_in[2];
    const float* K2    = (const float*)d_in[3];
    const float* R     = (const float*)d_in[4];
    const float* T     = (const float*)d_in[5];
    float* out = (float*)d_out;

    cudaFuncSetAttribute(k_gemm_mma, cudaFuncAttributeMaxDynamicSharedMemorySize, GEMM_SMEM);

    k_coef<<<Bb, 256>>>(K1, K2, R, T);
    k_row2<<<dim3(IBLK, Bb), 256>>>();
    k_cinv<<<(Bb * Nn + 255) / 256, 256>>>();
    k_conv_f<<<dim3(Cc / 4, Bb), 256>>>(f_src);
    k_gemm_mma<<<dim3(Cc / 128, Nn / 128, Bb), 256, GEMM_SMEM>>>(out);
}